// round 7
// baseline (speedup 1.0000x reference)
#include <cuda_runtime.h>

// Problem constants
#define BB 16
#define MM 4096
#define TT 4
#define DD 256
#define VV 40000
#define CONV 512
#define BD (BB*DD)          // 4096
#define BM (BB*MM)          // 65536
#define ECHUNK 32           // rows per fused gather block
#define NEB (MM/ECHUNK)     // 128 blocks per batch
#define LFB 64              // rows per logit_fast block
#define NLB (MM/LFB)        // 64 logit blocks per batch
#define TDR 256             // rows per tdot block

// ---------------- device scratch (allocation-free) ----------------
__device__ float g_logit[BM];
__device__ float g_uf[BD];
__device__ float g_part[NEB*BD];     // deterministic partial sums for o_k
__device__ float g_pmax[BB*NLB];
__device__ float g_psum[BB*NLB];
__device__ float g_smax[BB];
__device__ float g_sinv[BB];
__device__ float g_tdot[BB*VV];      // tdot[b][v] = C_h[v]·uf_b (current hop)
__device__ float g_hdot[BB*CONV];    // hdot[b][r] = hist[b,r]·uf_b (current hop)

// ---------------- kernels ----------------

// init uf = query_vector
__global__ void k_init(const float* __restrict__ qv){
    g_uf[blockIdx.x*DD + threadIdx.x] = qv[blockIdx.x*DD + threadIdx.x];
}

// tdot[b][v] = table[v,:]·uf[b,:]  — one thread per row, shuffle-free.
// uf held transposed in smem; 16 accumulators in registers; LDS.128 broadcast.
__global__ void __launch_bounds__(256) k_tdot(const float* __restrict__ table){
    __shared__ __align__(16) float suft[DD][16];   // [d][b]
    int t = threadIdx.x;
    for(int i = t; i < DD*BB; i += 256){
        int b = i >> 8, d = i & 255;
        suft[d][b] = g_uf[i];
    }
    __syncthreads();
    int r = blockIdx.x*TDR + t;
    if (r >= VV) return;
    const float4* row = reinterpret_cast<const float4*>(table + (size_t)r*DD);
    float4 a0 = make_float4(0,0,0,0), a1 = a0, a2 = a0, a3 = a0;
    #pragma unroll 4
    for(int c4 = 0; c4 < 64; ++c4){
        float4 v = row[c4];
        float vv[4] = {v.x, v.y, v.z, v.w};
        int d = c4*4;
        #pragma unroll
        for(int k = 0; k < 4; ++k){
            float vs = vv[k];
            float4 s0 = *reinterpret_cast<const float4*>(&suft[d+k][0]);
            float4 s1 = *reinterpret_cast<const float4*>(&suft[d+k][4]);
            float4 s2 = *reinterpret_cast<const float4*>(&suft[d+k][8]);
            float4 s3 = *reinterpret_cast<const float4*>(&suft[d+k][12]);
            a0.x += vs*s0.x; a0.y += vs*s0.y; a0.z += vs*s0.z; a0.w += vs*s0.w;
            a1.x += vs*s1.x; a1.y += vs*s1.y; a1.z += vs*s1.z; a1.w += vs*s1.w;
            a2.x += vs*s2.x; a2.y += vs*s2.y; a2.z += vs*s2.z; a2.w += vs*s2.w;
            a3.x += vs*s3.x; a3.y += vs*s3.y; a3.z += vs*s3.z; a3.w += vs*s3.w;
        }
    }
    float acc[16] = {a0.x,a0.y,a0.z,a0.w, a1.x,a1.y,a1.z,a1.w,
                     a2.x,a2.y,a2.z,a2.w, a3.x,a3.y,a3.z,a3.w};
    #pragma unroll
    for(int b = 0; b < 16; ++b) g_tdot[(size_t)b*VV + r] = acc[b];
}

// hdot[b][r] = hist[b,r]·uf[b]   (proven in R6)
__global__ void __launch_bounds__(256) k_hdot(const float* __restrict__ hist){
    int b = blockIdx.x;
    int warp = threadIdx.x >> 5, lane = threadIdx.x & 31;
    int d0 = lane*8;
    float ufr[8];
    #pragma unroll
    for(int i = 0; i < 8; ++i) ufr[i] = g_uf[b*DD + d0 + i];
    for(int r = warp; r < CONV; r += 8){
        const float4* row = reinterpret_cast<const float4*>(hist + ((size_t)b*CONV + r)*DD);
        float4 v0 = row[lane*2], v1 = row[lane*2 + 1];
        float a = v0.x*ufr[0] + v0.y*ufr[1] + v0.z*ufr[2] + v0.w*ufr[3]
                + v1.x*ufr[4] + v1.y*ufr[5] + v1.z*ufr[6] + v1.w*ufr[7];
        #pragma unroll
        for(int off = 16; off; off >>= 1) a += __shfl_down_sync(0xffffffffu, a, off);
        if (lane == 0) g_hdot[b*CONV + r] = a;
    }
}

// logits via tdot gather: logit = gp * (Σ_t tdot[tok] + hdot window) + softmax partials
__global__ void __launch_bounds__(64) k_logit_fast(
        const int* __restrict__ story, const int* __restrict__ kb_len,
        const int* __restrict__ conv_len, const float* __restrict__ gp,
        float* __restrict__ out_ext){
    int b = blockIdx.y;
    int m = blockIdx.x*LFB + threadIdx.x;
    const float* td = g_tdot + (size_t)b*VV;
    int4 tok = *reinterpret_cast<const int4*>(story + (size_t)(b*MM + m)*TT);
    float v = td[tok.x] + td[tok.y] + td[tok.z] + td[tok.w];
    int r = m - kb_len[b];
    if (r >= 0 && r < conv_len[b]) v += g_hdot[b*CONV + r];
    v *= gp[b*MM + m];
    g_logit[b*MM + m] = v;
    if (out_ext) out_ext[b*MM + m] = v;
    __shared__ float smax[2], ssum[2];
    int lane = threadIdx.x & 31, warp = threadIdx.x >> 5;
    float mx = v;
    #pragma unroll
    for(int off = 16; off; off >>= 1) mx = fmaxf(mx, __shfl_xor_sync(0xffffffffu, mx, off));
    float sm = expf(v - mx);
    #pragma unroll
    for(int off = 16; off; off >>= 1) sm += __shfl_xor_sync(0xffffffffu, sm, off);
    if (lane == 0){ smax[warp] = mx; ssum[warp] = sm; }
    __syncthreads();
    if (threadIdx.x == 0){
        float m2 = fmaxf(smax[0], smax[1]);
        float s2 = ssum[0]*expf(smax[0] - m2) + ssum[1]*expf(smax[1] - m2);
        g_pmax[b*NLB + blockIdx.x] = m2;
        g_psum[b*NLB + blockIdx.x] = s2;
    }
}

// combine per-block softmax partials (64 per batch): warp w = batch b   (proven)
__global__ void __launch_bounds__(512) k_stats(){
    int w = threadIdx.x >> 5, lane = threadIdx.x & 31;
    float m0 = g_pmax[w*NLB + lane], m1 = g_pmax[w*NLB + lane + 32];
    float s0 = g_psum[w*NLB + lane], s1 = g_psum[w*NLB + lane + 32];
    float mx = fmaxf(m0, m1);
    #pragma unroll
    for(int off = 16; off; off >>= 1) mx = fmaxf(mx, __shfl_xor_sync(0xffffffffu, mx, off));
    float sm = s0*expf(m0 - mx) + s1*expf(m1 - mx);
    #pragma unroll
    for(int off = 16; off; off >>= 1) sm += __shfl_xor_sync(0xffffffffu, sm, off);
    if (lane == 0){ g_smax[w] = mx; g_sinv[w] = 1.0f/sm; }
}

// FUSED gather + weighted partial-sum (+ optional emb store / psoft store):
//   emb_row = Σ_t table[tok] + hist window;  opart += p·gp·emb_row
// No 64MB materialization except the emb3 output (store_emb=1).
__global__ void __launch_bounds__(256) k_embo(
        int store_emb, const int* __restrict__ story, const int* __restrict__ kb_len,
        const int* __restrict__ conv_len, const float* __restrict__ hist,
        const float* __restrict__ table, float* __restrict__ emb3,
        const float* __restrict__ gp, float* __restrict__ psoft_out){
    int b = blockIdx.y, c = blockIdx.x;
    int m0 = c*ECHUNK;
    int t = threadIdx.x, mg = t >> 6, d4 = t & 63;
    __shared__ float sp[ECHUNK];
    __shared__ float4 sacc[4][64];
    if (t < ECHUNK){
        float p = expf(g_logit[b*MM + m0 + t] - g_smax[b]) * g_sinv[b];
        if (psoft_out) psoft_out[b*MM + m0 + t] = p;
        sp[t] = p * gp[b*MM + m0 + t];
    }
    __syncthreads();
    int start = kb_len[b], clen = conv_len[b];
    const float4* hb = reinterpret_cast<const float4*>(hist + (size_t)b*CONV*DD);
    const float4* t4 = reinterpret_cast<const float4*>(table);
    float* dst = emb3 + (size_t)b*MM*DD;
    float4 op = make_float4(0.f, 0.f, 0.f, 0.f);
    #pragma unroll 2
    for(int mi = mg; mi < ECHUNK; mi += 4){
        int m = m0 + mi;
        int4 tok = *reinterpret_cast<const int4*>(story + (size_t)(b*MM + m)*TT);
        float4 a = t4[(size_t)tok.x*64 + d4];
        float4 cc = t4[(size_t)tok.y*64 + d4];
        float4 e = t4[(size_t)tok.z*64 + d4];
        float4 f = t4[(size_t)tok.w*64 + d4];
        float4 acc;
        acc.x = a.x + cc.x + e.x + f.x;
        acc.y = a.y + cc.y + e.y + f.y;
        acc.z = a.z + cc.z + e.z + f.z;
        acc.w = a.w + cc.w + e.w + f.w;
        int r = m - start;
        if (r >= 0 && r < clen){
            float4 hv = hb[(size_t)r*64 + d4];
            acc.x += hv.x; acc.y += hv.y; acc.z += hv.z; acc.w += hv.w;
        }
        if (store_emb)
            reinterpret_cast<float4*>(dst + (size_t)m*DD)[d4] = acc;
        float w = sp[mi];
        op.x += w*acc.x; op.y += w*acc.y; op.z += w*acc.z; op.w += w*acc.w;
    }
    sacc[mg][d4] = op;
    __syncthreads();
    if (t < 64){
        float4 a0 = sacc[0][t], a1 = sacc[1][t], a2 = sacc[2][t], a3 = sacc[3][t];
        float4 r;
        r.x = a0.x + a1.x + a2.x + a3.x;
        r.y = a0.y + a1.y + a2.y + a3.y;
        r.z = a0.z + a1.z + a2.z + a3.z;
        r.w = a0.w + a1.w + a2.w + a3.w;
        reinterpret_cast<float4*>(g_part + (size_t)c*BD + b*DD)[t] = r;
    }
}

// uf += reduced partials; optionally also write to d_out
__global__ void k_uf_add(float* __restrict__ out){
    int b = blockIdx.x, d = threadIdx.x;
    float o = 0.f;
    #pragma unroll
    for(int c = 0; c < NEB; ++c) o += g_part[c*BD + b*DD + d];
    float v = g_uf[b*DD + d] + o;
    g_uf[b*DD + d] = v;
    if (out) out[b*DD + d] = v;
}

// ---------------- launcher ----------------
extern "C" void kernel_launch(void* const* d_in, const int* in_sizes, int n_in,
                              void* d_out, int out_size){
    const int*   story = (const int*)  d_in[0];
    const int*   kb    = (const int*)  d_in[1];
    const int*   cl    = (const int*)  d_in[2];
    const float* hist  = (const float*)d_in[4];
    const float* qv    = (const float*)d_in[5];
    const float* gp    = (const float*)d_in[6];
    const float* C     = (const float*)d_in[7];

    float* out        = (float*)d_out;
    float* out_psoft  = out;                 // (B, M)
    float* out_logits = out + BM;            // (B, M)
    float* out_uf     = out + 2*BM;          // (B, D)
    float* out_emb3   = out + 2*BM + BD;     // (B, M, D) = m_story[-1]

    // Only emb3 (an output) is ever materialized. Per hop:
    //   logits via tdot/hdot GEMV gather (proven correct in R6);
    //   o via fused gather + weighted partial sum (k_embo).
    // tdot_h for hop>0 reads C_h, which the preceding k_embo just streamed (L2-hot).

    const int TDG = (VV + TDR - 1)/TDR;   // 157
    k_init<<<BB, DD>>>(qv);

    // hop 0
    k_tdot<<<TDG, 256>>>(C);
    k_hdot<<<BB, 256>>>(hist);
    k_logit_fast<<<dim3(NLB, BB), LFB>>>(story, kb, cl, gp, nullptr);
    k_stats<<<1, 512>>>();
    k_embo<<<dim3(NEB, BB), 256>>>(0, story, kb, cl, hist, C + (size_t)1*VV*DD,
                                   out_emb3, gp, nullptr);
    k_uf_add<<<BB, DD>>>(nullptr);

    // hop 1
    k_tdot<<<TDG, 256>>>(C + (size_t)1*VV*DD);
    k_hdot<<<BB, 256>>>(hist);
    k_logit_fast<<<dim3(NLB, BB), LFB>>>(story, kb, cl, gp, nullptr);
    k_stats<<<1, 512>>>();
    k_embo<<<dim3(NEB, BB), 256>>>(0, story, kb, cl, hist, C + (size_t)2*VV*DD,
                                   out_emb3, gp, nullptr);
    k_uf_add<<<BB, DD>>>(nullptr);

    // hop 2 (writes logits, psoft, uf, emb3 outputs)
    k_tdot<<<TDG, 256>>>(C + (size_t)2*VV*DD);
    k_hdot<<<BB, 256>>>(hist);
    k_logit_fast<<<dim3(NLB, BB), LFB>>>(story, kb, cl, gp, out_logits);
    k_stats<<<1, 512>>>();
    k_embo<<<dim3(NEB, BB), 256>>>(1, story, kb, cl, hist, C + (size_t)3*VV*DD,
                                   out_emb3, gp, out_psoft);
    k_uf_add<<<BB, DD>>>(out_uf);
}

// round 8
// speedup vs baseline: 1.5360x; 1.5360x over previous
#include <cuda_runtime.h>

// Problem constants
#define BB 16
#define MM 4096
#define TT 4
#define DD 256
#define VV 40000
#define CONV 512
#define BD (BB*DD)          // 4096
#define BM (BB*MM)          // 65536
#define ECHUNK 32           // rows per embed/fused block
#define NEB (MM/ECHUNK)     // 128 blocks per batch
#define OCHUNK 32           // rows per k_o block
#define NOB (MM/OCHUNK)     // 128 o blocks per batch
#define LBLK 64             // rows per streaming-logit block
#define NLB (MM/LBLK)       // 64 logit blocks per batch
#define PMAXW 128           // stride of per-block softmax partial arrays
#define EMB_SZ ((size_t)BB*MM*DD)  // 16777216 elements (64MB)

// ---------------- device scratch (allocation-free) ----------------
__device__ float g_emb[2*16777216];  // emb[1],emb[2]; emb[3] in d_out; emb[0] never stored
__device__ float g_logit[BM];
__device__ float g_uf[BD];
__device__ float g_part[NOB*BD];
__device__ float g_pmax[BB*PMAXW];
__device__ float g_psum[BB*PMAXW];
__device__ float g_smax[BB];
__device__ float g_sinv[BB];

// ---------------- kernels ----------------

// init uf = query_vector
__global__ void k_init(const float* __restrict__ qv){
    g_uf[blockIdx.x*DD + threadIdx.x] = qv[blockIdx.x*DD + threadIdx.x];
}

// emb[b,m,:] = sum_t table[story[b,m,t],:] (+ history window); slot<2 -> g_emb, else emb3
__global__ void __launch_bounds__(256) k_embed(
        int slot, const int* __restrict__ story, const int* __restrict__ kb_len,
        const int* __restrict__ conv_len, const float* __restrict__ hist,
        const float* __restrict__ table, float* __restrict__ emb3){
    int b = blockIdx.y;
    int m0 = blockIdx.x * ECHUNK;
    int mg = threadIdx.x >> 6, d4 = threadIdx.x & 63;
    int start = kb_len[b], clen = conv_len[b];
    float* dst = ((slot < 2) ? (g_emb + (size_t)slot*EMB_SZ) : emb3) + (size_t)b*MM*DD;
    const float4* hb = reinterpret_cast<const float4*>(hist + (size_t)b*CONV*DD);
    const float4* t4 = reinterpret_cast<const float4*>(table);
    #pragma unroll 2
    for(int mi = 0; mi < ECHUNK; mi += 4){
        int m = m0 + mi + mg;
        int4 tok = *reinterpret_cast<const int4*>(story + (size_t)(b*MM + m)*TT);
        float4 a = t4[(size_t)tok.x*64 + d4];
        float4 c = t4[(size_t)tok.y*64 + d4];
        float4 e = t4[(size_t)tok.z*64 + d4];
        float4 f = t4[(size_t)tok.w*64 + d4];
        float4 acc;
        acc.x = a.x + c.x + e.x + f.x;
        acc.y = a.y + c.y + e.y + f.y;
        acc.z = a.z + c.z + e.z + f.z;
        acc.w = a.w + c.w + e.w + f.w;
        int r = m - start;
        if (r >= 0 && r < clen){
            float4 hv = hb[(size_t)r*64 + d4];
            acc.x += hv.x; acc.y += hv.y; acc.z += hv.z; acc.w += hv.w;
        }
        reinterpret_cast<float4*>(dst + (size_t)m*DD)[d4] = acc;
    }
}

// FUSED emb0 gather + hop-0 logits (emb0 never materialized):
//   logit[b,m] = gp * ((Σ_t C0[tok] + hist window) · uf[b]);  + online softmax partials
__global__ void __launch_bounds__(256) k_emb0_logit(
        const int* __restrict__ story, const int* __restrict__ kb_len,
        const int* __restrict__ conv_len, const float* __restrict__ hist,
        const float* __restrict__ table, const float* __restrict__ gp){
    int b = blockIdx.y, c = blockIdx.x;
    int m0 = c*ECHUNK;
    int t = threadIdx.x, mg = t >> 6, d4 = t & 63;
    int warp = t >> 5, lane = t & 31;
    __shared__ float4 su[64];
    __shared__ float sw[8][8];   // [warp][iter] partial dots
    if (t < 64) su[t] = reinterpret_cast<const float4*>(g_uf + b*DD)[t];
    __syncthreads();
    float4 u4 = su[d4];
    int start = kb_len[b], clen = conv_len[b];
    const float4* hb = reinterpret_cast<const float4*>(hist + (size_t)b*CONV*DD);
    const float4* t4 = reinterpret_cast<const float4*>(table);
    #pragma unroll
    for(int i = 0; i < 8; ++i){
        int m = m0 + i*4 + mg;
        int4 tok = *reinterpret_cast<const int4*>(story + (size_t)(b*MM + m)*TT);
        float4 a = t4[(size_t)tok.x*64 + d4];
        float4 cc = t4[(size_t)tok.y*64 + d4];
        float4 e = t4[(size_t)tok.z*64 + d4];
        float4 f = t4[(size_t)tok.w*64 + d4];
        float4 acc;
        acc.x = a.x + cc.x + e.x + f.x;
        acc.y = a.y + cc.y + e.y + f.y;
        acc.z = a.z + cc.z + e.z + f.z;
        acc.w = a.w + cc.w + e.w + f.w;
        int r = m - start;
        if (r >= 0 && r < clen){
            float4 hv = hb[(size_t)r*64 + d4];
            acc.x += hv.x; acc.y += hv.y; acc.z += hv.z; acc.w += hv.w;
        }
        float p = acc.x*u4.x + acc.y*u4.y + acc.z*u4.z + acc.w*u4.w;
        #pragma unroll
        for(int off = 16; off; off >>= 1) p += __shfl_down_sync(0xffffffffu, p, off);
        if (lane == 0) sw[warp][i] = p;
    }
    __syncthreads();
    if (t < 32){
        int r = t;   // row within block: r = 4*i + mg  ->  i = r>>2, mg = r&3
        float v = sw[2*(r&3)][r>>2] + sw[2*(r&3)+1][r>>2];
        v *= gp[b*MM + m0 + r];
        g_logit[b*MM + m0 + r] = v;
        float mx = v;
        #pragma unroll
        for(int off = 16; off; off >>= 1) mx = fmaxf(mx, __shfl_xor_sync(0xffffffffu, mx, off));
        float sm = expf(v - mx);
        #pragma unroll
        for(int off = 16; off; off >>= 1) sm += __shfl_xor_sync(0xffffffffu, sm, off);
        if (r == 0){ g_pmax[b*PMAXW + c] = mx; g_psum[b*PMAXW + c] = sm; }
    }
}

// streaming logits (hops 1,2): emb slot 0/1 from g_emb  [R5-proven]
__global__ void __launch_bounds__(256) k_logit(
        int slot, const float* __restrict__ gp, float* __restrict__ out_ext){
    int b = blockIdx.y;
    const float* emb = g_emb + (size_t)slot*EMB_SZ;
    const float* u = g_uf + b*DD;
    __shared__ float4 su[DD/4];
    __shared__ float smax[8], ssum[8];
    if (threadIdx.x < DD/4) su[threadIdx.x] = reinterpret_cast<const float4*>(u)[threadIdx.x];
    __syncthreads();
    int warp = threadIdx.x >> 5, lane = threadIdx.x & 31;
    int mbase = blockIdx.x*LBLK + warp*8;
    float lv[8];
    #pragma unroll
    for(int i = 0; i < 8; ++i){
        int m = mbase + i;
        const float4* row = reinterpret_cast<const float4*>(emb + ((size_t)b*MM + m)*DD);
        float4 v0 = row[lane], v1 = row[lane + 32];
        float4 u0 = su[lane], u1 = su[lane + 32];
        float acc = v0.x*u0.x + v0.y*u0.y + v0.z*u0.z + v0.w*u0.w
                  + v1.x*u1.x + v1.y*u1.y + v1.z*u1.z + v1.w*u1.w;
        #pragma unroll
        for(int off = 16; off; off >>= 1) acc += __shfl_down_sync(0xffffffffu, acc, off);
        if (lane == 0) acc *= gp[b*MM + m];
        lv[i] = acc;
    }
    if (lane == 0){
        float mx = lv[0];
        #pragma unroll
        for(int i = 1; i < 8; ++i) mx = fmaxf(mx, lv[i]);
        float sm = 0.f;
        #pragma unroll
        for(int i = 0; i < 8; ++i){
            g_logit[b*MM + mbase + i] = lv[i];
            if (out_ext) out_ext[b*MM + mbase + i] = lv[i];
            sm += expf(lv[i] - mx);
        }
        smax[warp] = mx; ssum[warp] = sm;
    }
    __syncthreads();
    if (threadIdx.x == 0){
        float mx = smax[0];
        #pragma unroll
        for(int w = 1; w < 8; ++w) mx = fmaxf(mx, smax[w]);
        float sm = 0.f;
        #pragma unroll
        for(int w = 0; w < 8; ++w) sm += ssum[w]*expf(smax[w] - mx);
        g_pmax[b*PMAXW + blockIdx.x] = mx;
        g_psum[b*PMAXW + blockIdx.x] = sm;
    }
}

// combine nblk per-block softmax partials per batch: warp w = batch b
__global__ void __launch_bounds__(512) k_stats(int nblk){
    int w = threadIdx.x >> 5, lane = threadIdx.x & 31;
    float mx = -3.0e38f, sm = 0.f;
    for(int i = lane; i < nblk; i += 32){
        float m = g_pmax[w*PMAXW + i], s = g_psum[w*PMAXW + i];
        float nm = fmaxf(mx, m);
        sm = sm*expf(mx - nm) + s*expf(m - nm);
        mx = nm;
    }
    #pragma unroll
    for(int off = 16; off; off >>= 1){
        float om = __shfl_xor_sync(0xffffffffu, mx, off);
        float os = __shfl_xor_sync(0xffffffffu, sm, off);
        float nm = fmaxf(mx, om);
        sm = sm*expf(mx - nm) + os*expf(om - nm);
        mx = nm;
    }
    if (lane == 0){ g_smax[w] = mx; g_sinv[w] = 1.0f/sm; }
}

// partial o_k with inline softmax; embC slot: 0/1 -> g_emb, 2 -> emb3 (d_out)  [proven]
__global__ void __launch_bounds__(256) k_o(
        int slot, const float* __restrict__ emb3, const float* __restrict__ gp,
        float* __restrict__ psoft_out){
    int b = blockIdx.y, c = blockIdx.x;
    const float* emb = (slot < 2) ? g_emb + (size_t)slot*EMB_SZ : emb3;
    __shared__ float sp[OCHUNK];
    __shared__ float4 sacc[4][64];
    int t = threadIdx.x, rg = t >> 6, d4 = t & 63;
    int m0 = c*OCHUNK;
    if (t < OCHUNK){
        float p = expf(g_logit[b*MM + m0 + t] - g_smax[b]) * g_sinv[b];
        if (psoft_out) psoft_out[b*MM + m0 + t] = p;
        sp[t] = p * gp[b*MM + m0 + t];
    }
    __syncthreads();
    const float4* base = reinterpret_cast<const float4*>(emb + ((size_t)b*MM + m0)*DD);
    float4 acc = make_float4(0.f, 0.f, 0.f, 0.f);
    #pragma unroll
    for(int mi = rg; mi < OCHUNK; mi += 4){
        float p = sp[mi];
        float4 v = base[(size_t)mi*64 + d4];
        acc.x += p*v.x; acc.y += p*v.y; acc.z += p*v.z; acc.w += p*v.w;
    }
    sacc[rg][d4] = acc;
    __syncthreads();
    if (t < 64){
        float4 a0 = sacc[0][t], a1 = sacc[1][t], a2 = sacc[2][t], a3 = sacc[3][t];
        float4 r;
        r.x = a0.x + a1.x + a2.x + a3.x;
        r.y = a0.y + a1.y + a2.y + a3.y;
        r.z = a0.z + a1.z + a2.z + a3.z;
        r.w = a0.w + a1.w + a2.w + a3.w;
        reinterpret_cast<float4*>(g_part + (size_t)c*BD + b*DD)[t] = r;
    }
}

// uf += reduced partials; optionally also write to d_out
__global__ void k_uf_add(float* __restrict__ out){
    int b = blockIdx.x, d = threadIdx.x;
    float o = 0.f;
    #pragma unroll
    for(int c = 0; c < NOB; ++c) o += g_part[c*BD + b*DD + d];
    float v = g_uf[b*DD + d] + o;
    g_uf[b*DD + d] = v;
    if (out) out[b*DD + d] = v;
}

// ---------------- launcher ----------------
extern "C" void kernel_launch(void* const* d_in, const int* in_sizes, int n_in,
                              void* d_out, int out_size){
    const int*   story = (const int*)  d_in[0];
    const int*   kb    = (const int*)  d_in[1];
    const int*   cl    = (const int*)  d_in[2];
    const float* hist  = (const float*)d_in[4];
    const float* qv    = (const float*)d_in[5];
    const float* gp    = (const float*)d_in[6];
    const float* C     = (const float*)d_in[7];

    float* out        = (float*)d_out;
    float* out_psoft  = out;                 // (B, M)
    float* out_logits = out + BM;            // (B, M)
    float* out_uf     = out + 2*BM;          // (B, D)
    float* out_emb3   = out + 2*BM + BD;     // (B, M, D) = m_story[-1]

    // Dead layer-loop eliminated (outputs never depend on it). emb[0] is used
    // only by hop-0 logits -> fused into its gather (never materialized).
    // embed h=1 launched LAST so emb[1] is L2-warm for o0 + logit1.

    k_init<<<BB, DD>>>(qv);
    k_embed<<<dim3(NEB, BB), 256>>>(2, story, kb, cl, hist, C + (size_t)3*VV*DD, out_emb3);
    k_embed<<<dim3(NEB, BB), 256>>>(1, story, kb, cl, hist, C + (size_t)2*VV*DD, out_emb3);
    k_embed<<<dim3(NEB, BB), 256>>>(0, story, kb, cl, hist, C + (size_t)1*VV*DD, out_emb3);

    // hop 0: fused gather-logit (no emb[0])
    k_emb0_logit<<<dim3(NEB, BB), 256>>>(story, kb, cl, hist, C, gp);
    k_stats<<<1, 512>>>(NEB);
    k_o<<<dim3(NOB, BB), 256>>>(0, out_emb3, gp, nullptr);     // embC = emb[1]
    k_uf_add<<<BB, DD>>>(nullptr);

    // hop 1: logit streams emb[1] (L2-hot from o0)
    k_logit<<<dim3(NLB, BB), 256>>>(0, gp, nullptr);
    k_stats<<<1, 512>>>(NLB);
    k_o<<<dim3(NOB, BB), 256>>>(1, out_emb3, gp, nullptr);     // embC = emb[2]
    k_uf_add<<<BB, DD>>>(nullptr);

    // hop 2: logit streams emb[2]; writes logits; o writes psoft; uf -> out
    k_logit<<<dim3(NLB, BB), 256>>>(1, gp, out_logits);
    k_stats<<<1, 512>>>(NLB);
    k_o<<<dim3(NOB, BB), 256>>>(2, out_emb3, gp, out_psoft);   // embC = emb[3] (d_out)
    k_uf_add<<<BB, DD>>>(out_uf);
}